// round 4
// baseline (speedup 1.0000x reference)
#include <cuda_runtime.h>
#include <cuda_bf16.h>

// Problem constants
#define BB 256   // batch
#define TT 64    // time steps
#define KK 512   // states

#define S_SLICES 16           // j-slices per step
#define JC (KK / S_SLICES)    // 32 j-rows per slice
#define TBATCH 32             // batches per CTA (16 warps x 2 batches)
#define NGROUPS (BB / TBATCH) // 8 batch groups
#define STEP_GRID (NGROUPS * S_SLICES) // 128 CTAs

#define L2E 1.4426950408889634f

// ---------------- device scratch (no allocations allowed) ----------------
__device__ float g_c2[KK * KK];   // coeff * log2(e)
__device__ float g_d2[KK * KK];   // bias  * log2(e)
__device__ float g_em0[KK];       // emission[:,0] after row softmax
__device__ float g_em1[KK];       // emission[:,1]
__device__ float g_post[BB * KK]; // current posterior
__device__ float g_part[S_SLICES * BB * KK]; // partial pbe per j-slice (8 MB)

__device__ __forceinline__ float ex2f(float x) {
    float r;
    asm("ex2.approx.ftz.f32 %0, %1;" : "=f"(r) : "f"(x));
    return r;
}

// ---------------- prep kernels ----------------
__global__ void scale_kernel(const float* __restrict__ coeff,
                             const float* __restrict__ bias) {
    int idx = blockIdx.x * blockDim.x + threadIdx.x; // grid 512 x 512
    g_c2[idx] = coeff[idx] * L2E;
    g_d2[idx] = bias[idx]  * L2E;
}

__global__ void em_kernel(const float* __restrict__ emission_w) {
    int k = threadIdx.x; // 1 block of 512
    float a = emission_w[2 * k + 0];
    float b = emission_w[2 * k + 1];
    float ea = ex2f(a * L2E);
    float eb = ex2f(b * L2E);
    float inv = __fdividef(1.0f, ea + eb);
    g_em0[k] = ea * inv;
    g_em1[k] = eb * inv;
}

// block-wide sum over 512 threads
__device__ __forceinline__ float block_sum(float v, float* sbuf) {
    int lane = threadIdx.x & 31, wid = threadIdx.x >> 5;
    #pragma unroll
    for (int o = 16; o; o >>= 1) v += __shfl_xor_sync(0xffffffffu, v, o);
    __syncthreads();               // protect sbuf reuse across calls
    if (lane == 0) sbuf[wid] = v;
    __syncthreads();
    if (wid == 0) {
        float t = (lane < 16) ? sbuf[lane] : 0.0f;
        #pragma unroll
        for (int o = 8; o; o >>= 1) t += __shfl_xor_sync(0xffffffffu, t, o);
        if (lane == 0) sbuf[0] = t;
    }
    __syncthreads();
    return sbuf[0];
}

// post0 = evidence(softmax(prior_w), x[:,0])
__global__ void init_kernel(const float* __restrict__ prior_w,
                            const float* __restrict__ x) {
    int b = blockIdx.x;        // grid 256
    int k = threadIdx.x;       // block 512
    __shared__ float red[32];
    float e = ex2f(prior_w[k] * L2E);
    float tot = block_sum(e, red);
    float prior = __fdividef(e, tot);
    float xt = x[b * TT + 0];
    float em = g_em0[k] + xt * (g_em1[k] - g_em0[k]); // (1-x)*em0 + x*em1
    float v = prior * em;
    float tv = block_sum(v, red);
    g_post[b * KK + k] = __fdividef(v, tv);
}

// ---------------- main step kernel ----------------
// CTA = (batch group bg of 32 batches) x (j-slice s of 32 rows).
// 16 warps, warp w handles batches b0=bg*32+2w, b1=b0+1.
// Each lane owns k = 128*i + 4*lane + c (i<4, c<4) -> 16 k-columns.
// Produces partial pbe for its j-slice into g_part[s][b][k].
__global__ void __launch_bounds__(512, 1) step_kernel() {
    extern __shared__ float sh[];
    float* sc = sh;              // [JC*KK] coeff*L2E rows
    float* sd = sh + JC * KK;    // [JC*KK] bias*L2E rows

    int bx  = blockIdx.x;
    int s   = bx & (S_SLICES - 1);
    int bg  = bx / S_SLICES;
    int tid = threadIdx.x;
    int j0  = s * JC;

    // cooperative load of 32 rows of c2/d2 (128 KB total), float4-vectorized
    {
        const float4* gc = (const float4*)(g_c2 + j0 * KK);
        const float4* gd = (const float4*)(g_d2 + j0 * KK);
        float4* sc4 = (float4*)sc;
        float4* sd4 = (float4*)sd;
        #pragma unroll
        for (int i = 0; i < (JC * KK / 4) / 512; i++) {
            sc4[tid + 512 * i] = gc[tid + 512 * i];
            sd4[tid + 512 * i] = gd[tid + 512 * i];
        }
    }
    __syncthreads();

    int w    = tid >> 5;
    int lane = tid & 31;
    int b0 = bg * TBATCH + w * 2;
    int b1 = b0 + 1;

    // preload post values for this slice's 32 j's (one per lane, shfl-broadcast)
    float p0 = g_post[b0 * KK + j0 + lane];
    float p1 = g_post[b1 * KK + j0 + lane];

    float acc0[16], acc1[16];
    #pragma unroll
    for (int i = 0; i < 16; i++) { acc0[i] = 0.0f; acc1[i] = 0.0f; }

    for (int j = 0; j < JC; j++) {
        float pj0 = __shfl_sync(0xffffffffu, p0, j);
        float pj1 = __shfl_sync(0xffffffffu, p1, j);
        const float4* c4 = (const float4*)(sc + j * KK);
        const float4* d4 = (const float4*)(sd + j * KK);

        float w0[16], w1[16];
        float z0 = 0.0f, z1 = 0.0f;
        #pragma unroll
        for (int i = 0; i < 4; i++) {
            float4 c = c4[lane + 32 * i];
            float4 d = d4[lane + 32 * i];
            float t;
            t = ex2f(fmaf(pj0, c.x, d.x)); w0[4*i+0] = t; z0 += t;
            t = ex2f(fmaf(pj0, c.y, d.y)); w0[4*i+1] = t; z0 += t;
            t = ex2f(fmaf(pj0, c.z, d.z)); w0[4*i+2] = t; z0 += t;
            t = ex2f(fmaf(pj0, c.w, d.w)); w0[4*i+3] = t; z0 += t;
            t = ex2f(fmaf(pj1, c.x, d.x)); w1[4*i+0] = t; z1 += t;
            t = ex2f(fmaf(pj1, c.y, d.y)); w1[4*i+1] = t; z1 += t;
            t = ex2f(fmaf(pj1, c.z, d.z)); w1[4*i+2] = t; z1 += t;
            t = ex2f(fmaf(pj1, c.w, d.w)); w1[4*i+3] = t; z1 += t;
        }
        #pragma unroll
        for (int o = 16; o; o >>= 1) {
            z0 += __shfl_xor_sync(0xffffffffu, z0, o);
            z1 += __shfl_xor_sync(0xffffffffu, z1, o);
        }
        float s0 = __fdividef(pj0, z0);
        float s1 = __fdividef(pj1, z1);
        #pragma unroll
        for (int i = 0; i < 16; i++) {
            acc0[i] = fmaf(s0, w0[i], acc0[i]);
            acc1[i] = fmaf(s1, w1[i], acc1[i]);
        }
    }

    // write partial pbe (coalesced float4 stores)
    float4* o0 = (float4*)(g_part + (size_t)(s * BB + b0) * KK);
    float4* o1 = (float4*)(g_part + (size_t)(s * BB + b1) * KK);
    #pragma unroll
    for (int i = 0; i < 4; i++) {
        o0[lane + 32 * i] = make_float4(acc0[4*i], acc0[4*i+1], acc0[4*i+2], acc0[4*i+3]);
        o1[lane + 32 * i] = make_float4(acc1[4*i], acc1[4*i+1], acc1[4*i+2], acc1[4*i+3]);
    }
}

// reduce partials over slices + evidence + row-normalize
__global__ void evid_kernel(const float* __restrict__ x, int t,
                            float* __restrict__ outp) {
    int b = blockIdx.x;   // grid 256
    int k = threadIdx.x;  // block 512
    __shared__ float red[32];
    float pbe = 0.0f;
    #pragma unroll
    for (int s = 0; s < S_SLICES; s++)
        pbe += g_part[(size_t)(s * BB + b) * KK + k];
    float xt = x[b * TT + t];
    float em = g_em0[k] + xt * (g_em1[k] - g_em0[k]);
    float v = pbe * em;
    float tot = block_sum(v, red);
    float r = __fdividef(v, tot);
    g_post[b * KK + k] = r;
    if (outp) outp[b * KK + k] = r;
}

// ---------------- launch ----------------
extern "C" void kernel_launch(void* const* d_in, const int* in_sizes, int n_in,
                              void* d_out, int out_size) {
    const float* x          = (const float*)d_in[0]; // [B,T]
    const float* prior_w    = (const float*)d_in[1]; // [K]
    const float* emission_w = (const float*)d_in[2]; // [K,2]
    const float* coeff      = (const float*)d_in[3]; // [K,K]
    const float* bias       = (const float*)d_in[4]; // [K,K]
    float* out = (float*)d_out;                      // [B,K]

    cudaFuncSetAttribute(step_kernel,
                         cudaFuncAttributeMaxDynamicSharedMemorySize,
                         2 * JC * KK * (int)sizeof(float));

    scale_kernel<<<KK * KK / 512, 512>>>(coeff, bias);
    em_kernel<<<1, KK>>>(emission_w);
    init_kernel<<<BB, KK>>>(prior_w, x);

    for (int t = 1; t < TT; t++) {
        step_kernel<<<STEP_GRID, 512, 2 * JC * KK * (int)sizeof(float)>>>();
        evid_kernel<<<BB, KK>>>(x, t, (t == TT - 1) ? out : nullptr);
    }
}